// round 14
// baseline (speedup 1.0000x reference)
#include <cuda_runtime.h>
#include <cuda_bf16.h>
#include <math.h>
#include <stdint.h>

#define NROWS 4096
#define HALF_N 2048
#define DD 512

#define ACH 16384                  // A chunk: 128 rows x 128B (one K-quarter)
#define BST 32768                  // B stage: 128 rows x 256B (one K-half)
#define OFFB 65536                 // B ring after 4 resident A chunks
#define SMEM_DYN (65536 + 3 * 32768 + 1024)
#define GRID_GEMM 144

// ---- device-global scratch ----
__device__ __align__(16) uint8_t g_q8[NROWS * DD];   // int8 quantized rows
__device__ float g_beta[NROWS];                      // sqrt(5)/|q_row|
__device__ float g_row_sum[NROWS];
__device__ float g_pos_acc;
__device__ unsigned int g_ctr;

// ============================================================
// K1: normalize -> int8 quantize; per-row beta; zero accumulators
// ============================================================
__global__ void k_normalize(const float* __restrict__ z1, const float* __restrict__ z2) {
    int row = blockIdx.x;
    const float* src = (row < HALF_N) ? (z1 + (size_t)row * DD)
                                      : (z2 + (size_t)(row - HALF_N) * DD);
    int t = threadIdx.x;
    float4 v = ((const float4*)src)[t];
    float ss = v.x * v.x + v.y * v.y + v.z * v.z + v.w * v.w;
    #pragma unroll
    for (int o = 16; o; o >>= 1) ss += __shfl_xor_sync(0xffffffffu, ss, o);

    __shared__ float warp_ss[4];
    __shared__ float s_inv;
    __shared__ int warp_qs[4];
    if ((t & 31) == 0) warp_ss[t >> 5] = ss;
    __syncthreads();
    if (t == 0) {
        float tot = warp_ss[0] + warp_ss[1] + warp_ss[2] + warp_ss[3];
        s_inv = 127.0f / fmaxf(sqrtf(tot), 1e-8f);
        g_row_sum[row] = 0.0f;
        if (row == 0) { g_pos_acc = 0.0f; g_ctr = 0u; }
    }
    __syncthreads();
    float inv = s_inv;
    int qa = __float2int_rn(fminf(fmaxf(v.x * inv, -127.0f), 127.0f));
    int qb = __float2int_rn(fminf(fmaxf(v.y * inv, -127.0f), 127.0f));
    int qc = __float2int_rn(fminf(fmaxf(v.z * inv, -127.0f), 127.0f));
    int qd = __float2int_rn(fminf(fmaxf(v.w * inv, -127.0f), 127.0f));
    uint32_t pk = (uint32_t)(qa & 0xFF) | ((uint32_t)(qb & 0xFF) << 8) |
                  ((uint32_t)(qc & 0xFF) << 16) | ((uint32_t)(qd & 0xFF) << 24);
    ((uint32_t*)(g_q8 + (size_t)row * DD))[t] = pk;

    int qs = qa * qa + qb * qb + qc * qc + qd * qd;
    #pragma unroll
    for (int o = 16; o; o >>= 1) qs += __shfl_xor_sync(0xffffffffu, qs, o);
    if ((t & 31) == 0) warp_qs[t >> 5] = qs;
    __syncthreads();
    if (t == 0) {
        int tq = warp_qs[0] + warp_qs[1] + warp_qs[2] + warp_qs[3];
        g_beta[row] = sqrtf(5.0f) * rsqrtf((float)tq);
    }
}

// ============================================================
// K2: persistent IMMA, 256 thr, cross-kk fragment double-buffer
// ============================================================
__device__ __forceinline__ void cp_async16(uint32_t saddr, const void* gptr) {
    asm volatile("cp.async.cg.shared.global [%0], [%1], 16;\n" :: "r"(saddr), "l"(gptr));
}
__device__ __forceinline__ void ldm_x4(uint32_t& r0, uint32_t& r1, uint32_t& r2, uint32_t& r3,
                                       uint32_t addr) {
    asm volatile("ldmatrix.sync.aligned.m8n8.x4.shared.b16 {%0,%1,%2,%3}, [%4];\n"
                 : "=r"(r0), "=r"(r1), "=r"(r2), "=r"(r3) : "r"(addr));
}
__device__ __forceinline__ void mma_s8(int* c, uint32_t a0, uint32_t a1, uint32_t a2,
                                       uint32_t a3, uint32_t b0, uint32_t b1) {
    asm volatile("mma.sync.aligned.m16n8k32.row.col.s32.s8.s8.s32 "
                 "{%0,%1,%2,%3}, {%4,%5,%6,%7}, {%8,%9}, {%0,%1,%2,%3};\n"
                 : "+r"(c[0]), "+r"(c[1]), "+r"(c[2]), "+r"(c[3])
                 : "r"(a0), "r"(a1), "r"(a2), "r"(a3), "r"(b0), "r"(b1));
}

__global__ void __launch_bounds__(256, 1) k_persist(float* __restrict__ out) {
    extern __shared__ uint8_t dsm_raw[];
    __shared__ float s_red[8];
    __shared__ int s_last;
    uint32_t raw_u = (uint32_t)__cvta_generic_to_shared(dsm_raw);
    uint32_t sm_u = (raw_u + 1023u) & ~1023u;

    // ---- CTA -> (bm, group-of-4-bn) ----
    int idx = blockIdx.x, bm = 0, gj = 0;
    #pragma unroll 1
    for (bm = 0; bm < 32; bm++) {
        int G = (32 - bm + 3) >> 2;
        if (idx < G) { gj = idx; break; }
        idx -= G;
    }
    int bn0 = bm + gj * 4;
    int n_tiles = 32 - bn0; if (n_tiles > 4) n_tiles = 4;
    int total = n_tiles * 2;                  // 32KB K-half stages
    int rowBase = bm * 128;

    int tid = threadIdx.x;
    int lane = tid & 31, warp = tid >> 5;
    int wm = warp >> 2, wn = warp & 3;        // 2x4 warp grid, 64x32 warp tiles

    // ---- loader geometry: B stage = 2048 x 16B, 8 per thread ----
    int lru[8], lcu[8], lch[8]; uint32_t lu[8];
    #pragma unroll
    for (int i = 0; i < 8; i++) {
        int u = tid + i * 256;
        lch[i] = u >> 10; lru[i] = (u >> 3) & 127; lcu[i] = u & 7;
        lu[i] = (uint32_t)(lru[i] * 128 + ((lcu[i] ^ (lru[i] & 7)) << 4) + lch[i] * 16384);
    }

    // ---- prologue: A resident (64KB, 16 x 16B per thread) ----
    #pragma unroll
    for (int i = 0; i < 16; i++) {
        int u = tid + i * 256;
        int c = u >> 10, w = u & 1023, r = w >> 3, cc = w & 7;
        uint32_t dst = sm_u + c * ACH + (uint32_t)(r * 128 + ((cc ^ (r & 7)) << 4));
        cp_async16(dst, g_q8 + ((size_t)(rowBase + r) << 9) + c * 128 + cc * 16);
    }
    asm volatile("cp.async.commit_group;\n");
    #pragma unroll
    for (int g = 0; g < 2; g++) {             // B stages 0,1 -> slots 0,1
        int bnB = (bn0 + (g >> 1)) * 128;
        int kOff = (g & 1) * 256;
        uint32_t so = sm_u + OFFB + (uint32_t)(g * BST);
        #pragma unroll
        for (int i = 0; i < 8; i++)
            cp_async16(so + lu[i],
                       g_q8 + ((size_t)(bnB + lru[i]) << 9) + kOff + lch[i] * 128 + lcu[i] * 16);
        asm volatile("cp.async.commit_group;\n");
    }

    // ---- precomputed within-chunk ldsm offsets ----
    int rB0 = wn * 32 + (lane & 7) + ((lane >> 4) << 3), rB1 = rB0 + 16;
    uint32_t cA = (uint32_t)(lane >> 4);
    uint32_t cB = (uint32_t)((lane >> 3) & 1);
    uint32_t adA[4][4], adB0[4], adB1[4];
    #pragma unroll
    for (int mt = 0; mt < 4; mt++) {
        int rA = wm * 64 + mt * 16 + (lane & 15);
        #pragma unroll
        for (int kk = 0; kk < 4; kk++)
            adA[mt][kk] = (uint32_t)(rA * 128) +
                          ((((uint32_t)(kk * 2) + cA) ^ (uint32_t)(rA & 7)) << 4);
    }
    #pragma unroll
    for (int kk = 0; kk < 4; kk++) {
        adB0[kk] = (uint32_t)(rB0 * 128) + ((((uint32_t)(kk * 2) + cB) ^ (uint32_t)(rB0 & 7)) << 4);
        adB1[kk] = (uint32_t)(rB1 * 128) + ((((uint32_t)(kk * 2) + cB) ^ (uint32_t)(rB1 & 7)) << 4);
    }

    // ---- hoisted row betas ----
    float betaR[4][2];
    #pragma unroll
    for (int mt = 0; mt < 4; mt++)
        #pragma unroll
        for (int h = 0; h < 2; h++)
            betaR[mt][h] = __ldg(&g_beta[rowBase + wm * 64 + mt * 16 + (lane >> 2) + h * 8]);

    int acc[4][4][4];
    #pragma unroll
    for (int i = 0; i < 4; i++)
        #pragma unroll
        for (int j = 0; j < 4; j++)
            #pragma unroll
            for (int k = 0; k < 4; k++) acc[i][j][k] = 0;

    uint32_t a[2][4][4], b[2][4][2];          // double-buffered fragments

    // fragment loader: q in [0,8): chunk q>>2, kk q&3
#define LDFRAG(q_, buf_, soA2_, soB2_) do {                                       \
        uint32_t sA_ = (soA2_) + (uint32_t)(((q_) >> 2) * ACH);                   \
        uint32_t sB_ = (soB2_) + (uint32_t)(((q_) >> 2) * 16384);                 \
        int kk_ = (q_) & 3;                                                       \
        ldm_x4(a[buf_][0][0], a[buf_][0][1], a[buf_][0][2], a[buf_][0][3], sA_ + adA[0][kk_]); \
        ldm_x4(a[buf_][1][0], a[buf_][1][1], a[buf_][1][2], a[buf_][1][3], sA_ + adA[1][kk_]); \
        ldm_x4(a[buf_][2][0], a[buf_][2][1], a[buf_][2][2], a[buf_][2][3], sA_ + adA[2][kk_]); \
        ldm_x4(a[buf_][3][0], a[buf_][3][1], a[buf_][3][2], a[buf_][3][3], sA_ + adA[3][kk_]); \
        ldm_x4(b[buf_][0][0], b[buf_][0][1], b[buf_][1][0], b[buf_][1][1], sB_ + adB0[kk_]);   \
        ldm_x4(b[buf_][2][0], b[buf_][2][1], b[buf_][3][0], b[buf_][3][1], sB_ + adB1[kk_]);   \
    } while (0)

    // ---- stage loop: stage f = tile (f>>1), K-half (f&1), slot f%3 ----
    int sCur = 0, sPre = 2;
    int lastF = total - 1;
    #pragma unroll 1
    for (int f = 0; f < total; f++) {
        if (f < lastF) asm volatile("cp.async.wait_group 1;\n");
        else           asm volatile("cp.async.wait_group 0;\n");
        __syncthreads();
        int g = f + 2;
        if (g < total) {
            int bnB = (bn0 + (g >> 1)) * 128;
            int kOff = (g & 1) * 256;
            uint32_t so = sm_u + OFFB + (uint32_t)(sPre * BST);
            #pragma unroll
            for (int i = 0; i < 8; i++)
                cp_async16(so + lu[i],
                           g_q8 + ((size_t)(bnB + lru[i]) << 9) + kOff + lch[i] * 128 + lcu[i] * 16);
            asm volatile("cp.async.commit_group;\n");
        }

        uint32_t soA2 = sm_u + (uint32_t)((f & 1) * 2 * ACH);
        uint32_t soB2 = sm_u + OFFB + (uint32_t)(sCur * BST);

        LDFRAG(0, 0, soA2, soB2);
        #pragma unroll
        for (int q = 0; q < 8; q++) {
            int cur = q & 1;
            if (q < 7) LDFRAG(q + 1, cur ^ 1, soA2, soB2);
            #pragma unroll
            for (int mt = 0; mt < 4; mt++)
                #pragma unroll
                for (int nt = 0; nt < 4; nt++)
                    mma_s8(acc[mt][nt], a[cur][mt][0], a[cur][mt][1], a[cur][mt][2],
                           a[cur][mt][3], b[cur][nt][0], b[cur][nt][1]);
        }
        if (++sCur == 3) sCur = 0;
        if (++sPre == 3) sPre = 0;

        if ((f & 1) == 1) {
            // ---- per-tile epilogue (barrier-free) ----
            int bn = bn0 + (f >> 1);
            bool diag = (bn == bm);
            bool isPos = (bn == bm + 16);
            float betaC[4][2];
            #pragma unroll
            for (int nt = 0; nt < 4; nt++)
                #pragma unroll
                for (int p = 0; p < 2; p++)
                    betaC[nt][p] = __ldg(&g_beta[bn * 128 + wn * 32 + nt * 8 + (lane & 3) * 2 + p]);

            float rowPart[4][2], colPart[4][2], pos_l = 0.0f;
            #pragma unroll
            for (int i = 0; i < 4; i++) {
                rowPart[i][0] = rowPart[i][1] = 0.0f;
                colPart[i][0] = colPart[i][1] = 0.0f;
            }
            #pragma unroll
            for (int mt = 0; mt < 4; mt++)
                #pragma unroll
                for (int nt = 0; nt < 4; nt++)
                    #pragma unroll
                    for (int j = 0; j < 4; j++) {
                        float lg = __int2float_rn(acc[mt][nt][j]) *
                                   betaR[mt][j >> 1] * betaC[nt][j & 1];
                        float e = __expf(lg);
                        if (diag || isPos) {
                            int rl = wm * 64 + mt * 16 + (lane >> 2) + (j >> 1) * 8;
                            int cl = wn * 32 + nt * 8 + (lane & 3) * 2 + (j & 1);
                            if (rl == cl) {
                                if (diag) e = 0.0f;
                                else pos_l += lg;
                            }
                        }
                        rowPart[mt][j >> 1] += e;
                        colPart[nt][j & 1] += e;
                        acc[mt][nt][j] = 0;
                    }

            #pragma unroll
            for (int mt = 0; mt < 4; mt++)
                #pragma unroll
                for (int q = 0; q < 2; q++) {
                    float v = rowPart[mt][q];
                    v += __shfl_xor_sync(0xffffffffu, v, 1);
                    v += __shfl_xor_sync(0xffffffffu, v, 2);
                    if ((lane & 3) == 0)
                        atomicAdd(&g_row_sum[rowBase + wm * 64 + mt * 16 + (lane >> 2) + q * 8], v);
                }
            if (!diag) {
                #pragma unroll
                for (int nt = 0; nt < 4; nt++)
                    #pragma unroll
                    for (int p = 0; p < 2; p++) {
                        float v = colPart[nt][p];
                        v += __shfl_xor_sync(0xffffffffu, v, 4);
                        v += __shfl_xor_sync(0xffffffffu, v, 8);
                        v += __shfl_xor_sync(0xffffffffu, v, 16);
                        if (lane < 4)
                            atomicAdd(&g_row_sum[bn * 128 + wn * 32 + nt * 8 + (lane & 3) * 2 + p], v);
                    }
            }
            if (isPos) {
                #pragma unroll
                for (int o = 16; o; o >>= 1) pos_l += __shfl_xor_sync(0xffffffffu, pos_l, o);
                if (lane == 0) atomicAdd(&g_pos_acc, pos_l);
            }
        }
    }
#undef LDFRAG

    // ---- finalize: last CTA computes the loss ----
    __threadfence();
    __syncthreads();
    if (tid == 0) {
        unsigned prev = atomicAdd(&g_ctr, 1u);
        s_last = (prev == (unsigned)(GRID_GEMM - 1)) ? 1 : 0;
    }
    __syncthreads();
    if (s_last) {
        __threadfence();
        float ls = 0.0f;
        #pragma unroll 1
        for (int r = tid; r < NROWS; r += 256) ls += logf(__ldcg(&g_row_sum[r]));
        #pragma unroll
        for (int o = 16; o; o >>= 1) ls += __shfl_xor_sync(0xffffffffu, ls, o);
        if (lane == 0) s_red[warp] = ls;
        __syncthreads();
        if (tid == 0) {
            float tot = 0.0f;
            #pragma unroll
            for (int i = 0; i < 8; i++) tot += s_red[i];
            float pos2 = __ldcg(&g_pos_acc) * 2.0f;
            out[0] = (tot - pos2) * (1.0f / (float)NROWS);
        }
    }
}

extern "C" void kernel_launch(void* const* d_in, const int* in_sizes, int n_in,
                              void* d_out, int out_size) {
    const float* z1 = (const float*)d_in[0];
    const float* z2 = (const float*)d_in[1];
    float* out = (float*)d_out;
    cudaFuncSetAttribute(k_persist, cudaFuncAttributeMaxDynamicSharedMemorySize, SMEM_DYN);
    k_normalize<<<NROWS, 128>>>(z1, z2);
    k_persist<<<GRID_GEMM, 256, SMEM_DYN>>>(out);
}

// round 15
// speedup vs baseline: 1.1065x; 1.1065x over previous
#include <cuda_runtime.h>
#include <cuda_bf16.h>
#include <math.h>
#include <stdint.h>

#define NROWS 4096
#define HALF_N 2048
#define DD 512

#define ACH 16384                  // A chunk: 128 rows x 128B (one K-quarter)
#define BST 65536                  // B stage: 128 rows x 512B (full K of one tile)
#define OFFB 65536                 // B double-buffer after 4 resident A chunks
#define SMEM_DYN (65536 + 2 * 65536 + 1024)
#define GRID_GEMM 144

// ---- device-global scratch ----
__device__ __align__(16) uint8_t g_q8[NROWS * DD];   // int8 quantized rows
__device__ float g_beta[NROWS];                      // sqrt(5)/|q_row|
__device__ float g_row_sum[NROWS];
__device__ float g_pos_acc;
__device__ unsigned int g_ctr;                       // finalize ticket (never reset)
__device__ unsigned int g_bar;                       // global barrier ticket (never reset)

__device__ __forceinline__ void cp_async16(uint32_t saddr, const void* gptr) {
    asm volatile("cp.async.cg.shared.global [%0], [%1], 16;\n" :: "r"(saddr), "l"(gptr));
}
__device__ __forceinline__ void ldm_x4(uint32_t& r0, uint32_t& r1, uint32_t& r2, uint32_t& r3,
                                       uint32_t addr) {
    asm volatile("ldmatrix.sync.aligned.m8n8.x4.shared.b16 {%0,%1,%2,%3}, [%4];\n"
                 : "=r"(r0), "=r"(r1), "=r"(r2), "=r"(r3) : "r"(addr));
}
__device__ __forceinline__ void mma_s8(int* c, uint32_t a0, uint32_t a1, uint32_t a2,
                                       uint32_t a3, uint32_t b0, uint32_t b1) {
    asm volatile("mma.sync.aligned.m16n8k32.row.col.s32.s8.s8.s32 "
                 "{%0,%1,%2,%3}, {%4,%5,%6,%7}, {%8,%9}, {%0,%1,%2,%3};\n"
                 : "+r"(c[0]), "+r"(c[1]), "+r"(c[2]), "+r"(c[3])
                 : "r"(a0), "r"(a1), "r"(a2), "r"(a3), "r"(b0), "r"(b1));
}

// ============================================================
// Single fused persistent kernel
// ============================================================
__global__ void __launch_bounds__(512, 1) k_persist(float* __restrict__ out,
                                                    const float* __restrict__ z1,
                                                    const float* __restrict__ z2) {
    extern __shared__ uint8_t dsm_raw[];
    __shared__ float s_red[16];
    __shared__ int s_last;
    uint32_t raw_u = (uint32_t)__cvta_generic_to_shared(dsm_raw);
    uint32_t sm_u = (raw_u + 1023u) & ~1023u;

    int tid = threadIdx.x;
    int lane = tid & 31, warp = tid >> 5;

    // ================= phase 0: zero accumulators =================
    for (int r = tid + blockIdx.x * 512; r < NROWS; r += GRID_GEMM * 512)
        g_row_sum[r] = 0.0f;                 // only CTAs 0..7 hit this
    if (blockIdx.x == 0 && tid == 0) g_pos_acc = 0.0f;

    // ================= phase 1: normalize + int8 quantize (warp per row) ====
    for (int row = blockIdx.x * 16 + warp; row < NROWS; row += GRID_GEMM * 16) {
        const float4* src = (const float4*)((row < HALF_N)
                            ? (z1 + (size_t)row * DD)
                            : (z2 + (size_t)(row - HALF_N) * DD));
        float4 v[4];
        float ss = 0.0f;
        #pragma unroll
        for (int i = 0; i < 4; i++) {
            v[i] = src[lane * 4 + i];
            ss += v[i].x * v[i].x + v[i].y * v[i].y + v[i].z * v[i].z + v[i].w * v[i].w;
        }
        #pragma unroll
        for (int o = 16; o; o >>= 1) ss += __shfl_xor_sync(0xffffffffu, ss, o);
        float inv = 127.0f / fmaxf(sqrtf(ss), 1e-8f);

        uint32_t pk[4];
        int qs = 0;
        #pragma unroll
        for (int i = 0; i < 4; i++) {
            int qa = __float2int_rn(fminf(fmaxf(v[i].x * inv, -127.0f), 127.0f));
            int qb = __float2int_rn(fminf(fmaxf(v[i].y * inv, -127.0f), 127.0f));
            int qc = __float2int_rn(fminf(fmaxf(v[i].z * inv, -127.0f), 127.0f));
            int qd = __float2int_rn(fminf(fmaxf(v[i].w * inv, -127.0f), 127.0f));
            qs += qa * qa + qb * qb + qc * qc + qd * qd;
            pk[i] = (uint32_t)(qa & 0xFF) | ((uint32_t)(qb & 0xFF) << 8) |
                    ((uint32_t)(qc & 0xFF) << 16) | ((uint32_t)(qd & 0xFF) << 24);
        }
        uint4 w4 = make_uint4(pk[0], pk[1], pk[2], pk[3]);
        ((uint4*)(g_q8 + (size_t)row * DD))[lane] = w4;
        #pragma unroll
        for (int o = 16; o; o >>= 1) qs += __shfl_xor_sync(0xffffffffu, qs, o);
        if (lane == 0) g_beta[row] = sqrtf(5.0f) * rsqrtf((float)qs);
    }

    // ================= phase 2: global software barrier (ticket) ============
    __syncthreads();
    if (tid == 0) {
        __threadfence();
        unsigned my = atomicAdd(&g_bar, 1u);
        unsigned target = (my / GRID_GEMM + 1u) * GRID_GEMM;
        unsigned cur;
        do {
            asm volatile("ld.acquire.gpu.global.u32 %0, [%1];"
                         : "=r"(cur) : "l"(&g_bar));
        } while (cur < target);
    }
    __syncthreads();

    // ================= phase 3: GEMM =================
    // ---- CTA -> (bm, group-of-4-bn) ----
    int idx = blockIdx.x, bm = 0, gj = 0;
    #pragma unroll 1
    for (bm = 0; bm < 32; bm++) {
        int G = (32 - bm + 3) >> 2;
        if (idx < G) { gj = idx; break; }
        idx -= G;
    }
    int bn0 = bm + gj * 4;
    int n_tiles = 32 - bn0; if (n_tiles > 4) n_tiles = 4;
    int rowBase = bm * 128;

    int wm = warp >> 2, wn = warp & 3;        // 4x4 warp grid, 32x32 warp tiles

    // ---- loader geometry: B stage = 4096 x 16B, 8 per thread ----
    int lru[8], lcu[8], lch[8]; uint32_t lu[8];
    #pragma unroll
    for (int i = 0; i < 8; i++) {
        int u = tid + i * 512;
        lch[i] = u >> 10; lru[i] = (u >> 3) & 127; lcu[i] = u & 7;
        lu[i] = (uint32_t)(lru[i] * 128 + ((lcu[i] ^ (lru[i] & 7)) << 4) + lch[i] * 16384);
    }

    // ---- prologue: A resident (64KB, 8 x 16B per thread) ----
    #pragma unroll
    for (int i = 0; i < 8; i++) {
        int u = tid + i * 512;
        int c = u >> 10, w = u & 1023, r = w >> 3, cc = w & 7;
        uint32_t dst = sm_u + c * ACH + (uint32_t)(r * 128 + ((cc ^ (r & 7)) << 4));
        cp_async16(dst, g_q8 + ((size_t)(rowBase + r) << 9) + c * 128 + cc * 16);
    }
    asm volatile("cp.async.commit_group;\n");
    {   // B tile 0 -> slot 0
        int bnB = bn0 * 128;
        uint32_t so = sm_u + OFFB;
        #pragma unroll
        for (int i = 0; i < 8; i++)
            cp_async16(so + lu[i],
                       g_q8 + ((size_t)(bnB + lru[i]) << 9) + lch[i] * 128 + lcu[i] * 16);
        asm volatile("cp.async.commit_group;\n");
    }

    // ---- precomputed within-chunk ldsm offsets ----
    int rA0 = wm * 32 + (lane & 15), rA1 = rA0 + 16;
    int rB0 = wn * 32 + (lane & 7) + ((lane >> 4) << 3), rB1 = rB0 + 16;
    uint32_t cA = (uint32_t)(lane >> 4);
    uint32_t cB = (uint32_t)((lane >> 3) & 1);
    uint32_t adA0[4], adA1[4], adB0[4], adB1[4];
    #pragma unroll
    for (int kk = 0; kk < 4; kk++) {
        adA0[kk] = (uint32_t)(rA0 * 128) + ((((uint32_t)(kk * 2) + cA) ^ (uint32_t)(rA0 & 7)) << 4);
        adA1[kk] = (uint32_t)(rA1 * 128) + ((((uint32_t)(kk * 2) + cA) ^ (uint32_t)(rA1 & 7)) << 4);
        adB0[kk] = (uint32_t)(rB0 * 128) + ((((uint32_t)(kk * 2) + cB) ^ (uint32_t)(rB0 & 7)) << 4);
        adB1[kk] = (uint32_t)(rB1 * 128) + ((((uint32_t)(kk * 2) + cB) ^ (uint32_t)(rB1 & 7)) << 4);
    }

    // ---- hoisted row betas ----
    float betaR[2][2];
    #pragma unroll
    for (int mt = 0; mt < 2; mt++)
        #pragma unroll
        for (int h = 0; h < 2; h++)
            betaR[mt][h] = __ldg(&g_beta[rowBase + wm * 32 + mt * 16 + (lane >> 2) + h * 8]);

    int acc[2][4][4];
    #pragma unroll
    for (int i = 0; i < 2; i++)
        #pragma unroll
        for (int j = 0; j < 4; j++)
            #pragma unroll
            for (int k = 0; k < 4; k++) acc[i][j][k] = 0;

    // ---- tile loop: one barrier per tile ----
    #pragma unroll 1
    for (int t = 0; t < n_tiles; t++) {
        asm volatile("cp.async.wait_group 0;\n");
        __syncthreads();
        if (t + 1 < n_tiles) {                // prefetch next tile's B into other slot
            int bnB = (bn0 + t + 1) * 128;
            uint32_t so = sm_u + OFFB + (uint32_t)(((t + 1) & 1) * BST);
            #pragma unroll
            for (int i = 0; i < 8; i++)
                cp_async16(so + lu[i],
                           g_q8 + ((size_t)(bnB + lru[i]) << 9) + lch[i] * 128 + lcu[i] * 16);
            asm volatile("cp.async.commit_group;\n");
        }

        uint32_t soB0 = sm_u + OFFB + (uint32_t)((t & 1) * BST);
        #pragma unroll
        for (int c = 0; c < 4; c++) {
            uint32_t soA = sm_u + (uint32_t)(c * ACH);
            uint32_t soB = soB0 + (uint32_t)(c * 16384);
            #pragma unroll
            for (int kk = 0; kk < 4; kk++) {
                uint32_t a[2][4], b[4][2];
                ldm_x4(a[0][0], a[0][1], a[0][2], a[0][3], soA + adA0[kk]);
                ldm_x4(a[1][0], a[1][1], a[1][2], a[1][3], soA + adA1[kk]);
                ldm_x4(b[0][0], b[0][1], b[1][0], b[1][1], soB + adB0[kk]);
                ldm_x4(b[2][0], b[2][1], b[3][0], b[3][1], soB + adB1[kk]);
                #pragma unroll
                for (int mt = 0; mt < 2; mt++)
                    #pragma unroll
                    for (int nt = 0; nt < 4; nt++)
                        mma_s8(acc[mt][nt], a[mt][0], a[mt][1], a[mt][2], a[mt][3],
                               b[nt][0], b[nt][1]);
            }
        }

        // ---- per-tile epilogue (barrier-free) ----
        int bn = bn0 + t;
        bool diag = (bn == bm);
        bool isPos = (bn == bm + 16);
        float betaC[4][2];
        #pragma unroll
        for (int nt = 0; nt < 4; nt++)
            #pragma unroll
            for (int p = 0; p < 2; p++)
                betaC[nt][p] = __ldg(&g_beta[bn * 128 + wn * 32 + nt * 8 + (lane & 3) * 2 + p]);

        float rowPart[2][2], colPart[4][2], pos_l = 0.0f;
        #pragma unroll
        for (int i = 0; i < 2; i++) rowPart[i][0] = rowPart[i][1] = 0.0f;
        #pragma unroll
        for (int i = 0; i < 4; i++) colPart[i][0] = colPart[i][1] = 0.0f;

        #pragma unroll
        for (int mt = 0; mt < 2; mt++)
            #pragma unroll
            for (int nt = 0; nt < 4; nt++)
                #pragma unroll
                for (int j = 0; j < 4; j++) {
                    float lg = __int2float_rn(acc[mt][nt][j]) *
                               betaR[mt][j >> 1] * betaC[nt][j & 1];
                    float e = __expf(lg);
                    if (diag || isPos) {
                        int rl = wm * 32 + mt * 16 + (lane >> 2) + (j >> 1) * 8;
                        int cl = wn * 32 + nt * 8 + (lane & 3) * 2 + (j & 1);
                        if (rl == cl) {
                            if (diag) e = 0.0f;
                            else pos_l += lg;
                        }
                    }
                    rowPart[mt][j >> 1] += e;
                    colPart[nt][j & 1] += e;
                    acc[mt][nt][j] = 0;
                }

        #pragma unroll
        for (int mt = 0; mt < 2; mt++)
            #pragma unroll
            for (int q = 0; q < 2; q++) {
                float v = rowPart[mt][q];
                v += __shfl_xor_sync(0xffffffffu, v, 1);
                v += __shfl_xor_sync(0xffffffffu, v, 2);
                if ((lane & 3) == 0)
                    atomicAdd(&g_row_sum[rowBase + wm * 32 + mt * 16 + (lane >> 2) + q * 8], v);
            }
        if (!diag) {
            #pragma unroll
            for (int nt = 0; nt < 4; nt++)
                #pragma unroll
                for (int p = 0; p < 2; p++) {
                    float v = colPart[nt][p];
                    v += __shfl_xor_sync(0xffffffffu, v, 4);
                    v += __shfl_xor_sync(0xffffffffu, v, 8);
                    v += __shfl_xor_sync(0xffffffffu, v, 16);
                    if (lane < 4)
                        atomicAdd(&g_row_sum[bn * 128 + wn * 32 + nt * 8 + (lane & 3) * 2 + p], v);
                }
        }
        if (isPos) {
            #pragma unroll
            for (int o = 16; o; o >>= 1) pos_l += __shfl_xor_sync(0xffffffffu, pos_l, o);
            if (lane == 0) atomicAdd(&g_pos_acc, pos_l);
        }
    }

    // ================= phase 4: finalize (last CTA, replay-safe ticket) =====
    __threadfence();
    __syncthreads();
    if (tid == 0) {
        unsigned prev = atomicAdd(&g_ctr, 1u);
        s_last = ((prev % GRID_GEMM) == (unsigned)(GRID_GEMM - 1)) ? 1 : 0;
    }
    __syncthreads();
    if (s_last) {
        __threadfence();
        float ls = 0.0f;
        #pragma unroll 1
        for (int r = tid; r < NROWS; r += 512) ls += logf(__ldcg(&g_row_sum[r]));
        #pragma unroll
        for (int o = 16; o; o >>= 1) ls += __shfl_xor_sync(0xffffffffu, ls, o);
        if (lane == 0) s_red[warp] = ls;
        __syncthreads();
        if (tid == 0) {
            float tot = 0.0f;
            #pragma unroll
            for (int i = 0; i < 16; i++) tot += s_red[i];
            float pos2 = __ldcg(&g_pos_acc) * 2.0f;
            out[0] = (tot - pos2) * (1.0f / (float)NROWS);
        }
    }
}

extern "C" void kernel_launch(void* const* d_in, const int* in_sizes, int n_in,
                              void* d_out, int out_size) {
    const float* z1 = (const float*)d_in[0];
    const float* z2 = (const float*)d_in[1];
    float* out = (float*)d_out;
    cudaFuncSetAttribute(k_persist, cudaFuncAttributeMaxDynamicSharedMemorySize, SMEM_DYN);
    k_persist<<<GRID_GEMM, 512, SMEM_DYN>>>(out, z1, z2);
}